// round 1
// baseline (speedup 1.0000x reference)
#include <cuda_runtime.h>
#include <cuda_bf16.h>
#include <math.h>

// Problem constants
#define BB   8
#define CIN  512
#define C1   256
#define DD   128
#define KK   32
#define NN   9216          // 96*96
#define SPLITK 16
#define KCHUNK (NN / SPLITK) // 576

// ---------------- scratch (device globals; no allocation) ----------------
__device__ float g_Theta[BB * C1 * NN];
__device__ float g_Phi  [BB * C1 * NN];
__device__ float g_G    [BB * C1 * NN];
__device__ float g_Fp   [SPLITK * BB * C1 * C1];  // split-K partials of f
__device__ float g_F    [BB * C1 * C1];           // softmaxed f
__device__ float g_Y    [BB * C1 * NN];
__device__ float g_Z    [BB * CIN * NN];
__device__ float g_ZD   [BB * DD * NN];
__device__ float g_Eacc [BB * KK * DD];
__device__ float g_Asum [BB * KK];
__device__ float g_Es   [BB * DD];
__device__ float g_gamma[BB * CIN];

// ---------------- zero the accumulated buffers ----------------
__global__ void zero_kernel() {
    int i = blockIdx.x * blockDim.x + threadIdx.x;
    if (i < BB * KK * DD) g_Eacc[i] = 0.f;
    if (i < BB * KK)      g_Asum[i] = 0.f;
    if (i < BB * DD)      g_Es[i]   = 0.f;
}

// ---------------- 128x128x8 register-tiled SGEMM (NN layout) ----------------
// C[b, m, n] = sum_k A[b?, m, k] * B[b, k, n] (+ bias[m]) (+ R[b, m, n])
template<bool RESID>
__global__ __launch_bounds__(256) void sgemm128(
    const float* __restrict__ Ag, long sA,
    const float* __restrict__ Bg, long sB,
    float* __restrict__ Cg, long sC,
    const float* __restrict__ bias,
    const float* __restrict__ Rg, long sR,
    int M, int N, int K)
{
    int b = blockIdx.z;
    const float* A = Ag + (long)b * sA;
    const float* Bm = Bg + (long)b * sB;
    float* C = Cg + (long)b * sC;
    const float* R = RESID ? (Rg + (long)b * sR) : nullptr;

    __shared__ float As[8][128];
    __shared__ float Bs[8][128];

    int tid = threadIdx.x;
    int m0 = blockIdx.y * 128, n0 = blockIdx.x * 128;
    int tx = tid & 15, ty = tid >> 4;

    float acc[8][8];
#pragma unroll
    for (int i = 0; i < 8; i++)
#pragma unroll
        for (int j = 0; j < 8; j++) acc[i][j] = 0.f;

    int arow = tid >> 1, akq = (tid & 1) * 4;   // A tile: 128 rows x 8 k
    int brow = tid >> 5, bnq = (tid & 31) * 4;  // B tile: 8 k x 128 n

    for (int k0 = 0; k0 < K; k0 += 8) {
        float4 av = *(const float4*)(A + (long)(m0 + arow) * K + k0 + akq);
        float4 bv = *(const float4*)(Bm + (long)(k0 + brow) * N + n0 + bnq);
        As[akq + 0][arow] = av.x;
        As[akq + 1][arow] = av.y;
        As[akq + 2][arow] = av.z;
        As[akq + 3][arow] = av.w;
        *(float4*)(&Bs[brow][bnq]) = bv;
        __syncthreads();
#pragma unroll
        for (int kk = 0; kk < 8; kk++) {
            float a[8], bb[8];
#pragma unroll
            for (int i = 0; i < 8; i++) a[i] = As[kk][(i >> 2) * 64 + ty * 4 + (i & 3)];
#pragma unroll
            for (int j = 0; j < 8; j++) bb[j] = Bs[kk][(j >> 2) * 64 + tx * 4 + (j & 3)];
#pragma unroll
            for (int i = 0; i < 8; i++)
#pragma unroll
                for (int j = 0; j < 8; j++) acc[i][j] += a[i] * bb[j];
        }
        __syncthreads();
    }

    // epilogue: two coalesced float4 stores per row-group
#pragma unroll
    for (int i = 0; i < 8; i++) {
        int m = m0 + (i >> 2) * 64 + ty * 4 + (i & 3);
        float bi = bias ? bias[m] : 0.f;
#pragma unroll
        for (int jj = 0; jj < 2; jj++) {
            int n = n0 + jj * 64 + tx * 4;
            float4 v;
            v.x = acc[i][jj * 4 + 0] + bi;
            v.y = acc[i][jj * 4 + 1] + bi;
            v.z = acc[i][jj * 4 + 2] + bi;
            v.w = acc[i][jj * 4 + 3] + bi;
            if (RESID) {
                float4 r = *(const float4*)(R + (long)m * N + n);
                v.x += r.x; v.y += r.y; v.z += r.z; v.w += r.w;
            }
            *(float4*)(C + (long)m * N + n) = v;
        }
    }
}

// ---------------- 64x64x16 NT GEMM with split-K partial outputs ----------------
// Fp[chunk, b, m, n] = sum_{k in chunk} A[b, m, k] * B[b, n, k]
__global__ __launch_bounds__(256) void sgemm_nt_split(
    const float* __restrict__ Ag, long sA,
    const float* __restrict__ Bg, long sB,
    float* __restrict__ Cp,
    int M, int N, int K)
{
    int bz = blockIdx.z;
    int b = bz / SPLITK, chunk = bz % SPLITK;
    const float* A = Ag + (long)b * sA;
    const float* Bm = Bg + (long)b * sB;
    float* C = Cp + ((long)chunk * BB + b) * ((long)M * N);

    __shared__ float As[16][64];
    __shared__ float Bs[16][64];

    int tid = threadIdx.x;
    int m0 = blockIdx.y * 64, n0 = blockIdx.x * 64;
    int tx = tid & 15, ty = tid >> 4;

    float acc[4][4];
#pragma unroll
    for (int i = 0; i < 4; i++)
#pragma unroll
        for (int j = 0; j < 4; j++) acc[i][j] = 0.f;

    int lrow = tid >> 2, lkq = (tid & 3) * 4;

    int kend = chunk * KCHUNK + KCHUNK;
    for (int k0 = chunk * KCHUNK; k0 < kend; k0 += 16) {
        float4 av = *(const float4*)(A + (long)(m0 + lrow) * K + k0 + lkq);
        float4 bv = *(const float4*)(Bm + (long)(n0 + lrow) * K + k0 + lkq);
        As[lkq + 0][lrow] = av.x; As[lkq + 1][lrow] = av.y;
        As[lkq + 2][lrow] = av.z; As[lkq + 3][lrow] = av.w;
        Bs[lkq + 0][lrow] = bv.x; Bs[lkq + 1][lrow] = bv.y;
        Bs[lkq + 2][lrow] = bv.z; Bs[lkq + 3][lrow] = bv.w;
        __syncthreads();
#pragma unroll
        for (int kk = 0; kk < 16; kk++) {
            float a[4], bb[4];
#pragma unroll
            for (int i = 0; i < 4; i++) a[i] = As[kk][ty * 4 + i];
#pragma unroll
            for (int j = 0; j < 4; j++) bb[j] = Bs[kk][tx * 4 + j];
#pragma unroll
            for (int i = 0; i < 4; i++)
#pragma unroll
                for (int j = 0; j < 4; j++) acc[i][j] += a[i] * bb[j];
        }
        __syncthreads();
    }
#pragma unroll
    for (int i = 0; i < 4; i++) {
        int m = m0 + ty * 4 + i;
        float4 v; v.x = acc[i][0]; v.y = acc[i][1]; v.z = acc[i][2]; v.w = acc[i][3];
        *(float4*)(C + (long)m * N + n0 + tx * 4) = v;
    }
}

// ---------------- row softmax over f (reduces split-K partials) ----------------
__global__ void softmax_rows(const float* __restrict__ Fp, float* __restrict__ F)
{
    int row = blockIdx.x;           // 0..BB*C1-1
    int t = threadIdx.x;            // 256
    int b = row >> 8, c = row & 255;
    long base = (long)b * C1 * C1 + (long)c * C1 + t;
    float v = 0.f;
#pragma unroll
    for (int ch = 0; ch < SPLITK; ch++)
        v += Fp[(long)ch * BB * C1 * C1 + base];

    __shared__ float sh[256];
    sh[t] = v; __syncthreads();
    for (int o = 128; o; o >>= 1) { if (t < o) sh[t] = fmaxf(sh[t], sh[t + o]); __syncthreads(); }
    float m = sh[0]; __syncthreads();
    float e = expf(v - m);
    sh[t] = e; __syncthreads();
    for (int o = 128; o; o >>= 1) { if (t < o) sh[t] += sh[t + o]; __syncthreads(); }
    float inv = 1.f / sh[0];
    F[base] = e * inv;
}

// ---------------- fused dist -> softmax(A) -> E accumulation ----------------
__global__ __launch_bounds__(256) void encode_kernel(
    const float* __restrict__ ZD,          // (B, D, N)
    const float* __restrict__ codewords,   // (K, D)
    const float* __restrict__ scale,       // (K)
    float* __restrict__ Eacc,              // (B, K, D)
    float* __restrict__ Asum)              // (B, K)
{
    int b = blockIdx.y;
    __shared__ float cs[KK][DD + 1];
    __shared__ float cn[KK];
    __shared__ float sc[KK];
    __shared__ float xs[DD][33];   // 128 x 32 tile of x, padded
    __shared__ float Ash[8][KK];

    int tid = threadIdx.x;
    int lane = tid & 31, wid = tid >> 5;

    for (int i = tid; i < KK * DD; i += 256) cs[i >> 7][i & 127] = codewords[i];
    if (tid < KK) sc[tid] = scale[tid];
    __syncthreads();
    if (tid < KK) {
        float s = 0.f;
        for (int d = 0; d < DD; d++) { float c = cs[tid][d]; s += c * c; }
        cn[tid] = s;
    }
    __syncthreads();

    float ereg[16];
#pragma unroll
    for (int i = 0; i < 16; i++) ereg[i] = 0.f;
    float asum_local = 0.f;
    int myk = tid >> 3, myd0 = tid & 7;

    for (int t = blockIdx.x; t < NN / 32; t += gridDim.x) {
        int n0 = t * 32;
        // load 128 x 32 x-tile (coalesced), store transposed-friendly
#pragma unroll
        for (int r = 0; r < 4; r++) {
            int d = (tid >> 3) + r * 32;
            int nq = (tid & 7) * 4;
            float4 v = *(const float4*)(ZD + ((long)b * DD + d) * NN + n0 + nq);
            xs[d][nq + 0] = v.x; xs[d][nq + 1] = v.y;
            xs[d][nq + 2] = v.z; xs[d][nq + 3] = v.w;
        }
        __syncthreads();

        for (int round = 0; round < 4; round++) {
            int n = round * 8 + wid;  // each warp owns one n
            float xx = 0.f;
            for (int d = lane; d < DD; d += 32) { float x = xs[d][n]; xx += x * x; }
            for (int o = 16; o; o >>= 1) xx += __shfl_xor_sync(0xffffffffu, xx, o);
            float dot = 0.f;
#pragma unroll 8
            for (int d = 0; d < DD; d++) dot += xs[d][n] * cs[lane][d];
            float s = sc[lane] * (xx - 2.f * dot + cn[lane]);
            float m = s;
            for (int o = 16; o; o >>= 1) m = fmaxf(m, __shfl_xor_sync(0xffffffffu, m, o));
            float e = __expf(s - m);
            float ssum = e;
            for (int o = 16; o; o >>= 1) ssum += __shfl_xor_sync(0xffffffffu, ssum, o);
            float a = e / ssum;
            Ash[wid][lane] = a;
            asum_local += a;
            __syncthreads();
#pragma unroll
            for (int nn = 0; nn < 8; nn++) {
                float av = Ash[nn][myk];
                int ncol = round * 8 + nn;
#pragma unroll
                for (int i = 0; i < 16; i++)
                    ereg[i] += av * xs[myd0 + 8 * i][ncol];
            }
            __syncthreads();
        }
    }
#pragma unroll
    for (int i = 0; i < 16; i++)
        atomicAdd(&Eacc[((long)b * KK + myk) * DD + myd0 + 8 * i], ereg[i]);
    atomicAdd(&Asum[b * KK + lane], asum_local);
}

// ---------------- BN over K channels + Es = sum_k relu(norm(E)) ----------------
__global__ void bn_es_kernel(const float* __restrict__ Eacc,
                             const float* __restrict__ Asum,
                             const float* __restrict__ codewords,
                             float* __restrict__ Es)
{
    int k = blockIdx.x;       // 0..31
    int tid = threadIdx.x;    // 256
    __shared__ double shs[256], shs2[256];
    float vals[4];
    double s = 0.0, s2 = 0.0;
#pragma unroll
    for (int i = 0; i < 4; i++) {
        int idx = tid + i * 256;            // (b,d) flat over 1024
        int b = idx >> 7, d = idx & 127;
        float v = Eacc[((long)b * KK + k) * DD + d] - Asum[b * KK + k] * codewords[k * DD + d];
        vals[i] = v; s += v; s2 += (double)v * v;
    }
    shs[tid] = s; shs2[tid] = s2; __syncthreads();
    for (int o = 128; o; o >>= 1) {
        if (tid < o) { shs[tid] += shs[tid + o]; shs2[tid] += shs2[tid + o]; }
        __syncthreads();
    }
    double mean = shs[0] / 1024.0;
    double var = shs2[0] / 1024.0 - mean * mean;
    float inv = rsqrtf((float)var + 1e-5f);
    float mf = (float)mean;
#pragma unroll
    for (int i = 0; i < 4; i++) {
        int idx = tid + i * 256;
        int b = idx >> 7, d = idx & 127;
        float e = (vals[i] - mf) * inv;
        if (e > 0.f) atomicAdd(&Es[b * DD + d], e);
    }
}

// ---------------- gamma = sigmoid(Es @ W_fc^T + b_fc) ----------------
__global__ void gamma_kernel(const float* __restrict__ Es,
                             const float* __restrict__ W_fc,
                             const float* __restrict__ b_fc,
                             float* __restrict__ gamma)
{
    int idx = blockIdx.x * blockDim.x + threadIdx.x;  // 0..BB*CIN-1
    int b = idx / CIN, c = idx % CIN;
    float s = b_fc[c];
    for (int d = 0; d < DD; d++) s += Es[b * DD + d] * W_fc[c * DD + d];
    gamma[idx] = 1.f / (1.f + expf(-s));
}

// ---------------- out = Z * gamma broadcast ----------------
__global__ void scale_out_kernel(const float* __restrict__ Z,
                                 const float* __restrict__ gamma,
                                 float* __restrict__ out)
{
    long idx = (long)blockIdx.x * blockDim.x + threadIdx.x;  // float4 index
    const long total4 = (long)BB * CIN * NN / 4;
    if (idx >= total4) return;
    float4 z = ((const float4*)Z)[idx];
    float gm = gamma[(idx * 4) / NN];
    z.x *= gm; z.y *= gm; z.z *= gm; z.w *= gm;
    ((float4*)out)[idx] = z;
}

// ---------------- launch ----------------
extern "C" void kernel_launch(void* const* d_in, const int* in_sizes, int n_in,
                              void* d_out, int out_size)
{
    const float* X        = (const float*)d_in[0];
    const float* W_theta  = (const float*)d_in[1];
    const float* b_theta  = (const float*)d_in[2];
    const float* W_phi    = (const float*)d_in[3];
    const float* b_phi    = (const float*)d_in[4];
    const float* W_g      = (const float*)d_in[5];
    const float* b_g      = (const float*)d_in[6];
    const float* W2       = (const float*)d_in[7];
    const float* b2       = (const float*)d_in[8];
    const float* W3       = (const float*)d_in[9];
    const float* b3       = (const float*)d_in[10];
    const float* codewords= (const float*)d_in[11];
    const float* scale    = (const float*)d_in[12];
    const float* W_fc     = (const float*)d_in[13];
    const float* b_fc     = (const float*)d_in[14];

    float *Theta, *Phi, *G, *Fp, *F, *Y, *Z, *ZD, *Eacc, *Asum, *Es, *gammaB;
    cudaGetSymbolAddress((void**)&Theta, g_Theta);
    cudaGetSymbolAddress((void**)&Phi,   g_Phi);
    cudaGetSymbolAddress((void**)&G,     g_G);
    cudaGetSymbolAddress((void**)&Fp,    g_Fp);
    cudaGetSymbolAddress((void**)&F,     g_F);
    cudaGetSymbolAddress((void**)&Y,     g_Y);
    cudaGetSymbolAddress((void**)&Z,     g_Z);
    cudaGetSymbolAddress((void**)&ZD,    g_ZD);
    cudaGetSymbolAddress((void**)&Eacc,  g_Eacc);
    cudaGetSymbolAddress((void**)&Asum,  g_Asum);
    cudaGetSymbolAddress((void**)&Es,    g_Es);
    cudaGetSymbolAddress((void**)&gammaB,g_gamma);

    const long sX  = (long)CIN * NN;   // X batch stride
    const long sC1 = (long)C1 * NN;    // (B, 256, N) stride
    const long sZD = (long)DD * NN;

    zero_kernel<<<128, 256>>>();

    // theta / phi / g : (256 x 512) @ (512 x 9216) per batch
    dim3 gQ(NN / 128, C1 / 128, BB);
    sgemm128<false><<<gQ, 256>>>(W_theta, 0, X, sX, Theta, sC1, b_theta, nullptr, 0, C1, NN, CIN);
    sgemm128<false><<<gQ, 256>>>(W_phi,   0, X, sX, Phi,   sC1, b_phi,   nullptr, 0, C1, NN, CIN);
    sgemm128<false><<<gQ, 256>>>(W_g,     0, X, sX, G,     sC1, b_g,     nullptr, 0, C1, NN, CIN);

    // f = theta @ phi^T, split-K
    dim3 gF(C1 / 64, C1 / 64, BB * SPLITK);
    sgemm_nt_split<<<gF, 256>>>(Theta, sC1, Phi, sC1, Fp, C1, C1, NN);
    softmax_rows<<<BB * C1, 256>>>(Fp, F);

    // y = f @ g
    dim3 gY(NN / 128, C1 / 128, BB);
    sgemm128<false><<<gY, 256>>>(F, (long)C1 * C1, G, sC1, Y, sC1, nullptr, nullptr, 0, C1, NN, C1);

    // z = W2 @ y + b2 + X
    dim3 gZ(NN / 128, CIN / 128, BB);
    sgemm128<true><<<gZ, 256>>>(W2, 0, Y, sC1, Z, sX, b2, X, sX, CIN, NN, C1);

    // z_ = W3 @ z + b3
    dim3 gD(NN / 128, DD / 128, BB);
    sgemm128<false><<<gD, 256>>>(W3, 0, Z, sX, ZD, sZD, b3, nullptr, 0, DD, NN, CIN);

    // encoding: dist -> softmax -> E partial sums
    encode_kernel<<<dim3(96, BB), 256>>>(ZD, codewords, scale, Eacc, Asum);

    // batch norm over K + Es
    bn_es_kernel<<<KK, 256>>>(Eacc, Asum, codewords, Es);

    // gamma
    gamma_kernel<<<(BB * CIN) / 256, 256>>>(Es, W_fc, b_fc, gammaB);

    // out = z * gamma
    long total4 = (long)BB * CIN * NN / 4;
    scale_out_kernel<<<(unsigned)((total4 + 255) / 256), 256>>>(Z, gammaB, (float*)d_out);
}

// round 2
// speedup vs baseline: 1.0003x; 1.0003x over previous
#include <cuda_runtime.h>
#include <cuda_bf16.h>
#include <math.h>

// Problem constants
#define BB   8
#define CIN  512
#define C1   256
#define DD   128
#define KK   32
#define NN   9216          // 96*96
#define SPLITK 16
#define KCHUNK (NN / SPLITK) // 576

// ---------------- scratch (device globals; no allocation) ----------------
__device__ float g_Theta[BB * C1 * NN];
__device__ float g_Phi  [BB * C1 * NN];
__device__ float g_G    [BB * C1 * NN];
__device__ float g_Fp   [SPLITK * BB * C1 * C1];  // split-K partials of f
__device__ float g_F    [BB * C1 * C1];           // softmaxed f
__device__ float g_Y    [BB * C1 * NN];
__device__ float g_Z    [BB * CIN * NN];
__device__ float g_ZD   [BB * DD * NN];
__device__ float g_Eacc [BB * KK * DD];
__device__ float g_Asum [BB * KK];
__device__ float g_Es   [BB * DD];
__device__ float g_gamma[BB * CIN];

// ---------------- zero the accumulated buffers ----------------
__global__ void zero_kernel() {
    int i = blockIdx.x * blockDim.x + threadIdx.x;
    if (i < BB * KK * DD) g_Eacc[i] = 0.f;
    if (i < BB * KK)      g_Asum[i] = 0.f;
    if (i < BB * DD)      g_Es[i]   = 0.f;
}

// ---------------- 128x128x8 register-tiled SGEMM (NN layout) ----------------
// C[b, m, n] = sum_k A[b?, m, k] * B[b, k, n] (+ bias[m]) (+ R[b, m, n])
template<bool RESID>
__global__ __launch_bounds__(256) void sgemm128(
    const float* __restrict__ Ag, long sA,
    const float* __restrict__ Bg, long sB,
    float* __restrict__ Cg, long sC,
    const float* __restrict__ bias,
    const float* __restrict__ Rg, long sR,
    int M, int N, int K)
{
    int b = blockIdx.z;
    const float* A = Ag + (long)b * sA;
    const float* Bm = Bg + (long)b * sB;
    float* C = Cg + (long)b * sC;
    const float* R = RESID ? (Rg + (long)b * sR) : nullptr;

    __shared__ float As[8][128];
    __shared__ float Bs[8][128];

    int tid = threadIdx.x;
    int m0 = blockIdx.y * 128, n0 = blockIdx.x * 128;
    int tx = tid & 15, ty = tid >> 4;

    float acc[8][8];
#pragma unroll
    for (int i = 0; i < 8; i++)
#pragma unroll
        for (int j = 0; j < 8; j++) acc[i][j] = 0.f;

    int arow = tid >> 1, akq = (tid & 1) * 4;   // A tile: 128 rows x 8 k
    int brow = tid >> 5, bnq = (tid & 31) * 4;  // B tile: 8 k x 128 n

    for (int k0 = 0; k0 < K; k0 += 8) {
        float4 av = *(const float4*)(A + (long)(m0 + arow) * K + k0 + akq);
        float4 bv = *(const float4*)(Bm + (long)(k0 + brow) * N + n0 + bnq);
        As[akq + 0][arow] = av.x;
        As[akq + 1][arow] = av.y;
        As[akq + 2][arow] = av.z;
        As[akq + 3][arow] = av.w;
        *(float4*)(&Bs[brow][bnq]) = bv;
        __syncthreads();
#pragma unroll
        for (int kk = 0; kk < 8; kk++) {
            float a[8], bb[8];
#pragma unroll
            for (int i = 0; i < 8; i++) a[i] = As[kk][(i >> 2) * 64 + ty * 4 + (i & 3)];
#pragma unroll
            for (int j = 0; j < 8; j++) bb[j] = Bs[kk][(j >> 2) * 64 + tx * 4 + (j & 3)];
#pragma unroll
            for (int i = 0; i < 8; i++)
#pragma unroll
                for (int j = 0; j < 8; j++) acc[i][j] += a[i] * bb[j];
        }
        __syncthreads();
    }

    // epilogue: two coalesced float4 stores per row-group
#pragma unroll
    for (int i = 0; i < 8; i++) {
        int m = m0 + (i >> 2) * 64 + ty * 4 + (i & 3);
        float bi = bias ? bias[m] : 0.f;
#pragma unroll
        for (int jj = 0; jj < 2; jj++) {
            int n = n0 + jj * 64 + tx * 4;
            float4 v;
            v.x = acc[i][jj * 4 + 0] + bi;
            v.y = acc[i][jj * 4 + 1] + bi;
            v.z = acc[i][jj * 4 + 2] + bi;
            v.w = acc[i][jj * 4 + 3] + bi;
            if (RESID) {
                float4 r = *(const float4*)(R + (long)m * N + n);
                v.x += r.x; v.y += r.y; v.z += r.z; v.w += r.w;
            }
            *(float4*)(C + (long)m * N + n) = v;
        }
    }
}

// ---------------- 64x64x16 NT GEMM with split-K partial outputs ----------------
// Fp[chunk, b, m, n] = sum_{k in chunk} A[b, m, k] * B[b, n, k]
__global__ __launch_bounds__(256) void sgemm_nt_split(
    const float* __restrict__ Ag, long sA,
    const float* __restrict__ Bg, long sB,
    float* __restrict__ Cp,
    int M, int N, int K)
{
    int bz = blockIdx.z;
    int b = bz / SPLITK, chunk = bz % SPLITK;
    const float* A = Ag + (long)b * sA;
    const float* Bm = Bg + (long)b * sB;
    float* C = Cp + ((long)chunk * BB + b) * ((long)M * N);

    __shared__ float As[16][64];
    __shared__ float Bs[16][64];

    int tid = threadIdx.x;
    int m0 = blockIdx.y * 64, n0 = blockIdx.x * 64;
    int tx = tid & 15, ty = tid >> 4;

    float acc[4][4];
#pragma unroll
    for (int i = 0; i < 4; i++)
#pragma unroll
        for (int j = 0; j < 4; j++) acc[i][j] = 0.f;

    int lrow = tid >> 2, lkq = (tid & 3) * 4;

    int kend = chunk * KCHUNK + KCHUNK;
    for (int k0 = chunk * KCHUNK; k0 < kend; k0 += 16) {
        float4 av = *(const float4*)(A + (long)(m0 + lrow) * K + k0 + lkq);
        float4 bv = *(const float4*)(Bm + (long)(n0 + lrow) * K + k0 + lkq);
        As[lkq + 0][lrow] = av.x; As[lkq + 1][lrow] = av.y;
        As[lkq + 2][lrow] = av.z; As[lkq + 3][lrow] = av.w;
        Bs[lkq + 0][lrow] = bv.x; Bs[lkq + 1][lrow] = bv.y;
        Bs[lkq + 2][lrow] = bv.z; Bs[lkq + 3][lrow] = bv.w;
        __syncthreads();
#pragma unroll
        for (int kk = 0; kk < 16; kk++) {
            float a[4], bb[4];
#pragma unroll
            for (int i = 0; i < 4; i++) a[i] = As[kk][ty * 4 + i];
#pragma unroll
            for (int j = 0; j < 4; j++) bb[j] = Bs[kk][tx * 4 + j];
#pragma unroll
            for (int i = 0; i < 4; i++)
#pragma unroll
                for (int j = 0; j < 4; j++) acc[i][j] += a[i] * bb[j];
        }
        __syncthreads();
    }
#pragma unroll
    for (int i = 0; i < 4; i++) {
        int m = m0 + ty * 4 + i;
        float4 v; v.x = acc[i][0]; v.y = acc[i][1]; v.z = acc[i][2]; v.w = acc[i][3];
        *(float4*)(C + (long)m * N + n0 + tx * 4) = v;
    }
}

// ---------------- row softmax over f (reduces split-K partials) ----------------
__global__ void softmax_rows(const float* __restrict__ Fp, float* __restrict__ F)
{
    int row = blockIdx.x;           // 0..BB*C1-1
    int t = threadIdx.x;            // 256
    int b = row >> 8, c = row & 255;
    long base = (long)b * C1 * C1 + (long)c * C1 + t;
    float v = 0.f;
#pragma unroll
    for (int ch = 0; ch < SPLITK; ch++)
        v += Fp[(long)ch * BB * C1 * C1 + base];

    __shared__ float sh[256];
    sh[t] = v; __syncthreads();
    for (int o = 128; o; o >>= 1) { if (t < o) sh[t] = fmaxf(sh[t], sh[t + o]); __syncthreads(); }
    float m = sh[0]; __syncthreads();
    float e = expf(v - m);
    sh[t] = e; __syncthreads();
    for (int o = 128; o; o >>= 1) { if (t < o) sh[t] += sh[t + o]; __syncthreads(); }
    float inv = 1.f / sh[0];
    F[base] = e * inv;
}

// ---------------- fused dist -> softmax(A) -> E accumulation ----------------
__global__ __launch_bounds__(256) void encode_kernel(
    const float* __restrict__ ZD,          // (B, D, N)
    const float* __restrict__ codewords,   // (K, D)
    const float* __restrict__ scale,       // (K)
    float* __restrict__ Eacc,              // (B, K, D)
    float* __restrict__ Asum)              // (B, K)
{
    int b = blockIdx.y;
    __shared__ float cs[KK][DD + 1];
    __shared__ float cn[KK];
    __shared__ float sc[KK];
    __shared__ float xs[DD][33];   // 128 x 32 tile of x, padded
    __shared__ float Ash[8][KK];

    int tid = threadIdx.x;
    int lane = tid & 31, wid = tid >> 5;

    for (int i = tid; i < KK * DD; i += 256) cs[i >> 7][i & 127] = codewords[i];
    if (tid < KK) sc[tid] = scale[tid];
    __syncthreads();
    if (tid < KK) {
        float s = 0.f;
        for (int d = 0; d < DD; d++) { float c = cs[tid][d]; s += c * c; }
        cn[tid] = s;
    }
    __syncthreads();

    float ereg[16];
#pragma unroll
    for (int i = 0; i < 16; i++) ereg[i] = 0.f;
    float asum_local = 0.f;
    int myk = tid >> 3, myd0 = tid & 7;

    for (int t = blockIdx.x; t < NN / 32; t += gridDim.x) {
        int n0 = t * 32;
        // load 128 x 32 x-tile (coalesced), store transposed-friendly
#pragma unroll
        for (int r = 0; r < 4; r++) {
            int d = (tid >> 3) + r * 32;
            int nq = (tid & 7) * 4;
            float4 v = *(const float4*)(ZD + ((long)b * DD + d) * NN + n0 + nq);
            xs[d][nq + 0] = v.x; xs[d][nq + 1] = v.y;
            xs[d][nq + 2] = v.z; xs[d][nq + 3] = v.w;
        }
        __syncthreads();

        for (int round = 0; round < 4; round++) {
            int n = round * 8 + wid;  // each warp owns one n
            float xx = 0.f;
            for (int d = lane; d < DD; d += 32) { float x = xs[d][n]; xx += x * x; }
            for (int o = 16; o; o >>= 1) xx += __shfl_xor_sync(0xffffffffu, xx, o);
            float dot = 0.f;
#pragma unroll 8
            for (int d = 0; d < DD; d++) dot += xs[d][n] * cs[lane][d];
            float s = sc[lane] * (xx - 2.f * dot + cn[lane]);
            float m = s;
            for (int o = 16; o; o >>= 1) m = fmaxf(m, __shfl_xor_sync(0xffffffffu, m, o));
            float e = __expf(s - m);
            float ssum = e;
            for (int o = 16; o; o >>= 1) ssum += __shfl_xor_sync(0xffffffffu, ssum, o);
            float a = e / ssum;
            Ash[wid][lane] = a;
            asum_local += a;
            __syncthreads();
#pragma unroll
            for (int nn = 0; nn < 8; nn++) {
                float av = Ash[nn][myk];
                int ncol = round * 8 + nn;
#pragma unroll
                for (int i = 0; i < 16; i++)
                    ereg[i] += av * xs[myd0 + 8 * i][ncol];
            }
            __syncthreads();
        }
    }
#pragma unroll
    for (int i = 0; i < 16; i++)
        atomicAdd(&Eacc[((long)b * KK + myk) * DD + myd0 + 8 * i], ereg[i]);
    atomicAdd(&Asum[b * KK + lane], asum_local);
}

// ---------------- BN over K channels + Es = sum_k relu(norm(E)) ----------------
__global__ void bn_es_kernel(const float* __restrict__ Eacc,
                             const float* __restrict__ Asum,
                             const float* __restrict__ codewords,
                             float* __restrict__ Es)
{
    int k = blockIdx.x;       // 0..31
    int tid = threadIdx.x;    // 256
    __shared__ double shs[256], shs2[256];
    float vals[4];
    double s = 0.0, s2 = 0.0;
#pragma unroll
    for (int i = 0; i < 4; i++) {
        int idx = tid + i * 256;            // (b,d) flat over 1024
        int b = idx >> 7, d = idx & 127;
        float v = Eacc[((long)b * KK + k) * DD + d] - Asum[b * KK + k] * codewords[k * DD + d];
        vals[i] = v; s += v; s2 += (double)v * v;
    }
    shs[tid] = s; shs2[tid] = s2; __syncthreads();
    for (int o = 128; o; o >>= 1) {
        if (tid < o) { shs[tid] += shs[tid + o]; shs2[tid] += shs2[tid + o]; }
        __syncthreads();
    }
    double mean = shs[0] / 1024.0;
    double var = shs2[0] / 1024.0 - mean * mean;
    float inv = rsqrtf((float)var + 1e-5f);
    float mf = (float)mean;
#pragma unroll
    for (int i = 0; i < 4; i++) {
        int idx = tid + i * 256;
        int b = idx >> 7, d = idx & 127;
        float e = (vals[i] - mf) * inv;
        if (e > 0.f) atomicAdd(&Es[b * DD + d], e);
    }
}

// ---------------- gamma = sigmoid(Es @ W_fc^T + b_fc) ----------------
__global__ void gamma_kernel(const float* __restrict__ Es,
                             const float* __restrict__ W_fc,
                             const float* __restrict__ b_fc,
                             float* __restrict__ gamma)
{
    int idx = blockIdx.x * blockDim.x + threadIdx.x;  // 0..BB*CIN-1
    int b = idx / CIN, c = idx % CIN;
    float s = b_fc[c];
    for (int d = 0; d < DD; d++) s += Es[b * DD + d] * W_fc[c * DD + d];
    gamma[idx] = 1.f / (1.f + expf(-s));
}

// ---------------- out = Z * gamma broadcast ----------------
__global__ void scale_out_kernel(const float* __restrict__ Z,
                                 const float* __restrict__ gamma,
                                 float* __restrict__ out)
{
    long idx = (long)blockIdx.x * blockDim.x + threadIdx.x;  // float4 index
    const long total4 = (long)BB * CIN * NN / 4;
    if (idx >= total4) return;
    float4 z = ((const float4*)Z)[idx];
    float gm = gamma[(idx * 4) / NN];
    z.x *= gm; z.y *= gm; z.z *= gm; z.w *= gm;
    ((float4*)out)[idx] = z;
}

// ---------------- launch ----------------
extern "C" void kernel_launch(void* const* d_in, const int* in_sizes, int n_in,
                              void* d_out, int out_size)
{
    const float* X        = (const float*)d_in[0];
    const float* W_theta  = (const float*)d_in[1];
    const float* b_theta  = (const float*)d_in[2];
    const float* W_phi    = (const float*)d_in[3];
    const float* b_phi    = (const float*)d_in[4];
    const float* W_g      = (const float*)d_in[5];
    const float* b_g      = (const float*)d_in[6];
    const float* W2       = (const float*)d_in[7];
    const float* b2       = (const float*)d_in[8];
    const float* W3       = (const float*)d_in[9];
    const float* b3       = (const float*)d_in[10];
    const float* codewords= (const float*)d_in[11];
    const float* scale    = (const float*)d_in[12];
    const float* W_fc     = (const float*)d_in[13];
    const float* b_fc     = (const float*)d_in[14];

    float *Theta, *Phi, *G, *Fp, *F, *Y, *Z, *ZD, *Eacc, *Asum, *Es, *gammaB;
    cudaGetSymbolAddress((void**)&Theta, g_Theta);
    cudaGetSymbolAddress((void**)&Phi,   g_Phi);
    cudaGetSymbolAddress((void**)&G,     g_G);
    cudaGetSymbolAddress((void**)&Fp,    g_Fp);
    cudaGetSymbolAddress((void**)&F,     g_F);
    cudaGetSymbolAddress((void**)&Y,     g_Y);
    cudaGetSymbolAddress((void**)&Z,     g_Z);
    cudaGetSymbolAddress((void**)&ZD,    g_ZD);
    cudaGetSymbolAddress((void**)&Eacc,  g_Eacc);
    cudaGetSymbolAddress((void**)&Asum,  g_Asum);
    cudaGetSymbolAddress((void**)&Es,    g_Es);
    cudaGetSymbolAddress((void**)&gammaB,g_gamma);

    const long sX  = (long)CIN * NN;   // X batch stride
    const long sC1 = (long)C1 * NN;    // (B, 256, N) stride
    const long sZD = (long)DD * NN;

    zero_kernel<<<128, 256>>>();

    // theta / phi / g : (256 x 512) @ (512 x 9216) per batch
    dim3 gQ(NN / 128, C1 / 128, BB);
    sgemm128<false><<<gQ, 256>>>(W_theta, 0, X, sX, Theta, sC1, b_theta, nullptr, 0, C1, NN, CIN);
    sgemm128<false><<<gQ, 256>>>(W_phi,   0, X, sX, Phi,   sC1, b_phi,   nullptr, 0, C1, NN, CIN);
    sgemm128<false><<<gQ, 256>>>(W_g,     0, X, sX, G,     sC1, b_g,     nullptr, 0, C1, NN, CIN);

    // f = theta @ phi^T, split-K
    dim3 gF(C1 / 64, C1 / 64, BB * SPLITK);
    sgemm_nt_split<<<gF, 256>>>(Theta, sC1, Phi, sC1, Fp, C1, C1, NN);
    softmax_rows<<<BB * C1, 256>>>(Fp, F);

    // y = f @ g
    dim3 gY(NN / 128, C1 / 128, BB);
    sgemm128<false><<<gY, 256>>>(F, (long)C1 * C1, G, sC1, Y, sC1, nullptr, nullptr, 0, C1, NN, C1);

    // z = W2 @ y + b2 + X
    dim3 gZ(NN / 128, CIN / 128, BB);
    sgemm128<true><<<gZ, 256>>>(W2, 0, Y, sC1, Z, sX, b2, X, sX, CIN, NN, C1);

    // z_ = W3 @ z + b3
    dim3 gD(NN / 128, DD / 128, BB);
    sgemm128<false><<<gD, 256>>>(W3, 0, Z, sX, ZD, sZD, b3, nullptr, 0, DD, NN, CIN);

    // encoding: dist -> softmax -> E partial sums
    encode_kernel<<<dim3(96, BB), 256>>>(ZD, codewords, scale, Eacc, Asum);

    // batch norm over K + Es
    bn_es_kernel<<<KK, 256>>>(Eacc, Asum, codewords, Es);

    // gamma
    gamma_kernel<<<(BB * CIN) / 256, 256>>>(Es, W_fc, b_fc, gammaB);

    // out = z * gamma
    long total4 = (long)BB * CIN * NN / 4;
    scale_out_kernel<<<(unsigned)((total4 + 255) / 256), 256>>>(Z, gammaB, (float*)d_out);
}